// round 2
// baseline (speedup 1.0000x reference)
#include <cuda_runtime.h>
#include <cstdint>

// Polar encoder, N=8192, K=4096, BS=8192.
// Codeword = [zeros(4096), u_row]; then 13 butterfly XOR stages:
//   stage s: x[p] ^= x[p + 2^s] for all p with bit s of p clear.
// Bit-packed: 256 uint32 words per row, one warp per row, 8 words per lane.
// Word index j = lane*8 + k  (k = 0..7).
//   d = 1,2,4,8,16      -> intra-word shift/mask XOR
//   d = 32,64,128       -> intra-thread word XOR (k-distance 1,2,4)
//   d = 256..4096       -> __shfl_xor over lanes (mask 1,2,4,8,16)

#define NN   8192
#define KK   4096
#define BSZ  8192
#define WARPS_PER_BLOCK 8

__global__ __launch_bounds__(256)
void polar_encode_kernel(const float* __restrict__ u, float* __restrict__ out) {
    __shared__ unsigned smem[WARPS_PER_BLOCK * 256];

    const int warp = threadIdx.x >> 5;
    const int lane = threadIdx.x & 31;
    const int row  = blockIdx.x * WARPS_PER_BLOCK + warp;

    const float* __restrict__ urow = u + (size_t)row * KK;

    unsigned w[8];

    // ---- 1. Pack input bits. Words 0..127 (first 4096 elements) are zero
    //         (frozen positions). Words 128..255 hold u packed LSB-first.
    //         Word 128+i is owned by lane 16 + (i>>3) at k = i&7.
    #pragma unroll
    for (int k = 0; k < 8; k++) {
        unsigned myw = 0u;
        #pragma unroll
        for (int g = 0; g < 16; g++) {
            const int i = g * 8 + k;                       // 0..127
            const float v = urow[i * 32 + lane];           // coalesced 128B
            const unsigned b = __ballot_sync(0xffffffffu, v != 0.0f);
            if (lane == 16 + g) myw = b;
        }
        w[k] = myw;                                        // lanes 0..15 keep 0
    }

    // ---- 2. Intra-word butterfly stages: d = 1, 2, 4, 8, 16.
    //         Bits p with (p & d) == 0 get XORed with bit p+d.
    #pragma unroll
    for (int k = 0; k < 8; k++) {
        unsigned x = w[k];
        x ^= (x >> 1)  & 0x55555555u;
        x ^= (x >> 2)  & 0x33333333u;
        x ^= (x >> 4)  & 0x0F0F0F0Fu;
        x ^= (x >> 8)  & 0x00FF00FFu;
        x ^= (x >> 16);                // (x>>16) already fits the 0x0000FFFF mask
        w[k] = x;
    }

    // ---- 3. Intra-thread word stages: word distances 1, 2, 4 (d = 32, 64, 128).
    w[0] ^= w[1];  w[2] ^= w[3];  w[4] ^= w[5];  w[6] ^= w[7];   // D=1
    w[0] ^= w[2];  w[1] ^= w[3];  w[4] ^= w[6];  w[5] ^= w[7];   // D=2
    w[0] ^= w[4];  w[1] ^= w[5];  w[2] ^= w[6];  w[3] ^= w[7];   // D=4

    // ---- 4. Cross-lane stages: word distances 8,16,32,64,128 (d = 256..4096).
    //         Lane with (lane & m) == 0 absorbs partner lane^m.
    #pragma unroll
    for (int m = 1; m <= 16; m <<= 1) {
        #pragma unroll
        for (int k = 0; k < 8; k++) {
            const unsigned p = __shfl_xor_sync(0xffffffffu, w[k], m);
            if ((lane & m) == 0) w[k] ^= p;
        }
    }

    // ---- 5. Stage words in shared, then expand bits -> float4 stores.
    unsigned* s = smem + warp * 256;
    #pragma unroll
    for (int k = 0; k < 8; k++) s[lane * 8 + k] = w[k];
    __syncwarp();

    float4* __restrict__ orow = (float4*)(out + (size_t)row * NN);
    #pragma unroll 8
    for (int i = 0; i < 64; i++) {
        // Elements [i*128, i*128+128): lane writes 4 consecutive floats.
        const unsigned word = s[i * 4 + (lane >> 3)];      // smem broadcast, conflict-free
        const int b = (lane & 7) * 4;
        float4 f;
        f.x = ((word >> (b + 0)) & 1u) ? 1.0f : 0.0f;
        f.y = ((word >> (b + 1)) & 1u) ? 1.0f : 0.0f;
        f.z = ((word >> (b + 2)) & 1u) ? 1.0f : 0.0f;
        f.w = ((word >> (b + 3)) & 1u) ? 1.0f : 0.0f;
        orow[i * 32 + lane] = f;                            // coalesced STG.128
    }
}

extern "C" void kernel_launch(void* const* d_in, const int* in_sizes, int n_in,
                              void* d_out, int out_size) {
    // d_in[0]: u         (float32, BS*K)
    // d_in[1]: info_pos  (int32)  -- structurally [4096, 8192), unused
    // d_in[2]: ind_gather(int32)  -- structurally fixed butterfly, unused
    const float* u = (const float*)d_in[0];
    float* out = (float*)d_out;
    (void)in_sizes; (void)n_in; (void)out_size;

    polar_encode_kernel<<<BSZ / WARPS_PER_BLOCK, 256>>>(u, out);
}

// round 4
// speedup vs baseline: 1.0564x; 1.0564x over previous
#include <cuda_runtime.h>
#include <cstdint>

// Polar encoder, N=8192, K=4096, BS=8192.
// frozen = [0,4096) => codeword = [y, y] with y = 12-stage Arikan transform of u.
// Transform = tensor-product of F over 12 address bits => stages commute and
// address bits may be mapped arbitrarily onto storage dimensions.
//
// Storage map (per warp = one row): u float index a (12 bits),
//   a = 128*q + 4*lane + c   (q = load-instr 0..31, c = float4 component)
//   word t = q>>3 (2 bits: a11,a10), bit = 4*(q&7) + c (5 bits: a9..a7, a1..a0),
//   lane = a6..a2.
// Stage mechanisms:
//   a0,a1      -> intra-word XOR, shifts 1,2
//   a2..a6     -> __shfl_xor masks 1,2,4,8,16
//   a7,a8,a9   -> intra-word XOR, shifts 4,8,16
//   a10,a11    -> intra-thread word XOR
// Pack and expand are per-lane only: no ballots, no shared memory.

#define NN   8192
#define KK   4096
#define BSZ  8192

__global__ __launch_bounds__(128)
void polar_encode_kernel(const float4* __restrict__ u4, float* __restrict__ out) {
    const int warp = threadIdx.x >> 5;
    const int lane = threadIdx.x & 31;
    const int row  = blockIdx.x * 4 + warp;

    const float4* __restrict__ urow4 = u4 + (size_t)row * (KK / 4);

    unsigned w[4];

    // ---- 1. Load (coalesced float4) + arithmetic bit-pack.
    //         Values are exactly 0.0f / 1.0f, so nib = x + 2y + 4z + 8w is exact.
    #pragma unroll
    for (int t = 0; t < 4; t++) {
        float4 f[8];
        #pragma unroll
        for (int r = 0; r < 8; r++)
            f[r] = urow4[(t * 8 + r) * 32 + lane];      // 8 independent 16B loads
        unsigned acc = 0u;
        #pragma unroll
        for (int r = 0; r < 8; r++) {
            float nf = fmaf(8.0f, f[r].w,
                       fmaf(4.0f, f[r].z,
                       fmaf(2.0f, f[r].y, f[r].x)));
            acc |= ((unsigned)__float2int_rn(nf)) << (4 * r);
        }
        w[t] = acc;
    }

    // ---- 2. Intra-word stages: address bits a0,a1 (shift 1,2) and a7,a8,a9
    //         (shift 4,8,16). Dest = bit-clear position absorbs bit-set partner.
    #pragma unroll
    for (int t = 0; t < 4; t++) {
        unsigned x = w[t];
        x ^= (x >> 1)  & 0x55555555u;
        x ^= (x >> 2)  & 0x33333333u;
        x ^= (x >> 4)  & 0x0F0F0F0Fu;
        x ^= (x >> 8)  & 0x00FF00FFu;
        x ^= (x >> 16);
        w[t] = x;
    }

    // ---- 3. Cross-lane stages: address bits a2..a6 (shfl_xor masks 1..16).
    #pragma unroll
    for (int m = 1; m <= 16; m <<= 1) {
        #pragma unroll
        for (int t = 0; t < 4; t++) {
            const unsigned p = __shfl_xor_sync(0xffffffffu, w[t], m);
            if ((lane & m) == 0) w[t] ^= p;
        }
    }

    // ---- 4. Intra-thread word stages: address bits a10, a11.
    w[0] ^= w[1];  w[2] ^= w[3];   // a10: t-bit0 clear absorbs +1
    w[0] ^= w[2];  w[1] ^= w[3];   // a11: t-bit1 clear absorbs +2

    // ---- 5. Expand bits -> floats, store both halves (codeword = [y, y]).
    //         Store instr j = 8t + r covers floats [128j, 128j+128); lane's
    //         float4 comes from its OWN word w[t], nibble r. Fully coalesced.
    float4* __restrict__ o0 = (float4*)(out + (size_t)row * NN);
    float4* __restrict__ o1 = (float4*)(out + (size_t)row * NN + KK);

    const unsigned ONE = 0x3F800000u;
    #pragma unroll
    for (int t = 0; t < 4; t++) {
        #pragma unroll
        for (int r = 0; r < 8; r++) {
            const unsigned nib = (w[t] >> (4 * r)) & 0xFu;
            float4 f;
            f.x = __uint_as_float((nib & 1u)        * ONE);
            f.y = __uint_as_float(((nib >> 1) & 1u) * ONE);
            f.z = __uint_as_float(((nib >> 2) & 1u) * ONE);
            f.w = __uint_as_float(((nib >> 3) & 1u) * ONE);
            const int j = t * 8 + r;
            o0[j * 32 + lane] = f;
            o1[j * 32 + lane] = f;
        }
    }
}

extern "C" void kernel_launch(void* const* d_in, const int* in_sizes, int n_in,
                              void* d_out, int out_size) {
    // d_in[0]: u (float32, BS*K); d_in[1]/d_in[2]: structurally constant, unused.
    const float4* u4 = (const float4*)d_in[0];
    float* out = (float*)d_out;
    (void)in_sizes; (void)n_in; (void)out_size;

    polar_encode_kernel<<<BSZ / 4, 128>>>(u4, out);
}